// round 6
// baseline (speedup 1.0000x reference)
#include <cuda_runtime.h>
#include <math.h>

// Block floating-point quantization (block_size=16, mantissa_bits=8).
// Persistent grid-stride kernel: 1184 CTAs (148 SMs x 8) loop over 1024-float4
// tiles. 4 consecutive lanes share one 16-elem block (one float4 each); every
// LDG.128 fully warp-coalesced; 4 front-batched loads per iteration (MLP_p1=4,
// sustained across iterations by the loop). No wave transitions, no tail raggedness.

#define TPB 256
#define CHUNKS 4
#define TILE (TPB * CHUNKS)   // 1024 float4 per tile
#define NCTA 1184             // 148 SMs * 8 CTAs/SM

__device__ __forceinline__ float absmax4(float4 v) {
    return fmaxf(fmaxf(fabsf(v.x), fabsf(v.y)), fmaxf(fabsf(v.z), fabsf(v.w)));
}

__device__ __forceinline__ int bfp_exp(float a) {
    int ef = (__float_as_int(a) >> 23) & 0xFF;
    return (ef != 0) ? (ef - 127) : ((a > 0.0f) ? ilogbf(a) : 0);
}

__device__ __forceinline__ float4 bfp_quant(float4 v, int e) {
    int eb = e - 7;
    float s  = __int_as_float((eb + 127) << 23);
    float is = __int_as_float((127 - eb) << 23);
    float4 r;
    r.x = fminf(fmaxf(rintf(v.x * is), -128.0f), 127.0f) * s;
    r.y = fminf(fmaxf(rintf(v.y * is), -128.0f), 127.0f) * s;
    r.z = fminf(fmaxf(rintf(v.z * is), -128.0f), 127.0f) * s;
    r.w = fminf(fmaxf(rintf(v.w * is), -128.0f), 127.0f) * s;
    return r;
}

__global__ __launch_bounds__(TPB) void bfp_quant_kernel(
    const float4* __restrict__ in, float4* __restrict__ out, int n4)
{
    int ntiles = n4 / TILE;     // full tiles (16384 for this shape)

    for (int tile = blockIdx.x; tile < ntiles; tile += gridDim.x) {
        int base = tile * TILE + threadIdx.x;

        float4 v[CHUNKS];
        #pragma unroll
        for (int c = 0; c < CHUNKS; c++) v[c] = __ldcs(in + base + c * TPB);

        float a[CHUNKS];
        #pragma unroll
        for (int c = 0; c < CHUNKS; c++) a[c] = absmax4(v[c]);
        #pragma unroll
        for (int c = 0; c < CHUNKS; c++) a[c] = fmaxf(a[c], __shfl_xor_sync(0xffffffffu, a[c], 1));
        #pragma unroll
        for (int c = 0; c < CHUNKS; c++) a[c] = fmaxf(a[c], __shfl_xor_sync(0xffffffffu, a[c], 2));

        #pragma unroll
        for (int c = 0; c < CHUNKS; c++) {
            float4 r = bfp_quant(v[c], bfp_exp(a[c]));
            __stcs(out + base + c * TPB, r);
        }
    }

    // remainder (none for this shape: n4 % TILE == 0); handled by CTA 0
    int rem_base = ntiles * TILE;
    if (blockIdx.x == 0 && rem_base < n4) {
        for (int i = rem_base + threadIdx.x; i < n4; i += TPB) {
            float4 v = __ldcs(in + i);
            float a = absmax4(v);
            a = fmaxf(a, __shfl_xor_sync(0xffffffffu, a, 1));
            a = fmaxf(a, __shfl_xor_sync(0xffffffffu, a, 2));
            __stcs(out + i, bfp_quant(v, bfp_exp(a)));
        }
    }
}

extern "C" void kernel_launch(void* const* d_in, const int* in_sizes, int n_in,
                              void* d_out, int out_size)
{
    const float4* x = (const float4*)d_in[0];
    float4* out = (float4*)d_out;
    int n = in_sizes[0];           // 4*4096*4096 = 67108864
    int n4 = n / 4;                // 16777216 float4
    int ntiles = n4 / TILE;
    int blocks = NCTA < ntiles ? NCTA : (ntiles > 0 ? ntiles : 1);
    bfp_quant_kernel<<<blocks, TPB>>>(x, out, n4);
}

// round 7
// speedup vs baseline: 1.1273x; 1.1273x over previous
#include <cuda_runtime.h>
#include <math.h>

// Block floating-point quantization (block_size=16, mantissa_bits=8).
// 256-bit vector loads/stores (sm_100+ v8.f32): each thread handles
// CHUNKS=2 groups of 8 consecutive floats; 2 consecutive lanes share one
// 16-element block (single shfl_xor(1) for the block max). Every warp
// memory instruction is 1KB contiguous (8 full 128B lines, 100% sectors).

#define TPB 256
#define CHUNKS 2
#define TILE_OCT (TPB * CHUNKS)   // 8-float groups per CTA = 512 (16KB)

__device__ __forceinline__ void ld256_cs(const float* p, float r[8]) {
    asm("ld.global.cs.v8.f32 {%0,%1,%2,%3,%4,%5,%6,%7}, [%8];"
        : "=f"(r[0]), "=f"(r[1]), "=f"(r[2]), "=f"(r[3]),
          "=f"(r[4]), "=f"(r[5]), "=f"(r[6]), "=f"(r[7])
        : "l"(p));
}

__device__ __forceinline__ void st256_cs(float* p, const float r[8]) {
    asm volatile("st.global.cs.v8.f32 [%0], {%1,%2,%3,%4,%5,%6,%7,%8};"
        :: "l"(p),
           "f"(r[0]), "f"(r[1]), "f"(r[2]), "f"(r[3]),
           "f"(r[4]), "f"(r[5]), "f"(r[6]), "f"(r[7])
        : "memory");
}

__device__ __forceinline__ float absmax8(const float r[8]) {
    float a01 = fmaxf(fabsf(r[0]), fabsf(r[1]));
    float a23 = fmaxf(fabsf(r[2]), fabsf(r[3]));
    float a45 = fmaxf(fabsf(r[4]), fabsf(r[5]));
    float a67 = fmaxf(fabsf(r[6]), fabsf(r[7]));
    return fmaxf(fmaxf(a01, a23), fmaxf(a45, a67));
}

__device__ __forceinline__ int bfp_exp(float a) {
    int ef = (__float_as_int(a) >> 23) & 0xFF;
    return (ef != 0) ? (ef - 127) : ((a > 0.0f) ? ilogbf(a) : 0);
}

__device__ __forceinline__ void bfp_quant8(float r[8], int e) {
    int eb = e - 7;
    float s  = __int_as_float((eb + 127) << 23);
    float is = __int_as_float((127 - eb) << 23);
    #pragma unroll
    for (int k = 0; k < 8; k++)
        r[k] = fminf(fmaxf(rintf(r[k] * is), -128.0f), 127.0f) * s;
}

__global__ __launch_bounds__(TPB) void bfp_quant_kernel(
    const float* __restrict__ in, float* __restrict__ out, int noct)
{
    int base = blockIdx.x * TILE_OCT + threadIdx.x;   // oct index (8 floats)

    if (base + (CHUNKS - 1) * TPB < noct) {
        // ---- full-tile fast path ----
        float v0[8], v1[8];
        ld256_cs(in + (size_t)base * 8, v0);
        ld256_cs(in + (size_t)(base + TPB) * 8, v1);

        float a0 = absmax8(v0);
        float a1 = absmax8(v1);
        a0 = fmaxf(a0, __shfl_xor_sync(0xffffffffu, a0, 1));
        a1 = fmaxf(a1, __shfl_xor_sync(0xffffffffu, a1, 1));

        bfp_quant8(v0, bfp_exp(a0));
        bfp_quant8(v1, bfp_exp(a1));

        st256_cs(out + (size_t)base * 8, v0);
        st256_cs(out + (size_t)(base + TPB) * 8, v1);
    } else {
        // ---- tail path (last CTA only) ----
        #pragma unroll
        for (int c = 0; c < CHUNKS; c++) {
            int o = base + c * TPB;
            bool pred = o < noct;
            float v[8];
            if (pred) ld256_cs(in + (size_t)o * 8, v);
            else {
                #pragma unroll
                for (int k = 0; k < 8; k++) v[k] = 0.0f;
            }
            float a = absmax8(v);
            a = fmaxf(a, __shfl_xor_sync(0xffffffffu, a, 1));
            if (pred) {
                bfp_quant8(v, bfp_exp(a));
                st256_cs(out + (size_t)o * 8, v);
            }
        }
    }
}

extern "C" void kernel_launch(void* const* d_in, const int* in_sizes, int n_in,
                              void* d_out, int out_size)
{
    const float* x = (const float*)d_in[0];
    float* out = (float*)d_out;
    int n = in_sizes[0];             // 4*4096*4096 = 67108864
    int noct = n / 8;                // 8388608 groups of 8 floats
    int blocks = (noct + TILE_OCT - 1) / TILE_OCT;   // 16384
    bfp_quant_kernel<<<blocks, TPB>>>(x, out, noct);
}